// round 3
// baseline (speedup 1.0000x reference)
#include <cuda_runtime.h>
#include <cuda_bf16.h>
#include <math.h>

#define NN 50000
#define NE 800000
#define C 128
#define OUTC 16
#define NG 128
#define SB 512
#define NBLK ((NN + SB - 1) / SB)   // 98

// -------- device scratch (no allocations allowed) --------
__device__ int   d_is64;
__device__ int   d_cnt[NN];          // incoming-edge counts
__device__ int   d_off[NN + 1];      // CSR offsets
__device__ int   d_cur[NN];          // fill cursors
__device__ int   d_srcs[NE];         // src ids grouped by dst
__device__ int   d_part[256];        // scan partials
__device__ float d_dis[NN];
__device__ __align__(16) float d_hp[(size_t)NN * C];
__device__ __align__(16) float d_h [(size_t)NN * C];
__device__ float d_pool[NG * C];
__device__ int   d_gcnt[NG];

// index accessor: int64 vs int32 edge/batch arrays
__device__ __forceinline__ int eidx(const void* p, int pos) {
    return d_is64 ? (int)((const long long*)p)[pos] : ((const int*)p)[pos];
}

// ---------------------------------------------------------------------------
// dtype sniff: as int64, the odd 32-bit words (high halves) are all zero.
__global__ void k_sniff(const unsigned int* __restrict__ w) {
    int allz = 1;
    #pragma unroll
    for (int i = 0; i < 32; i++)
        if (w[2 * i + 1] != 0u) allz = 0;
    d_is64 = allz;
}

// zero per-call state
__global__ void k_setup() {
    int i = blockIdx.x * blockDim.x + threadIdx.x;
    if (i < NN) d_cnt[i] = 0;
    if (i < NG * C) d_pool[i] = 0.0f;
    if (i < NG) d_gcnt[i] = 0;
}

// count incoming edges per dst
__global__ void k_count(const void* __restrict__ ei) {
    int e = blockIdx.x * blockDim.x + threadIdx.x;
    if (e >= NE) return;
    atomicAdd(&d_cnt[eidx(ei, NE + e)], 1);
}

// scan stage 1: per-block exclusive scan of d_cnt -> d_off, totals -> d_part
__global__ void k_scan1() {
    __shared__ int s[SB];
    int t = threadIdx.x;
    int i = blockIdx.x * SB + t;
    int v = (i < NN) ? d_cnt[i] : 0;
    s[t] = v;
    __syncthreads();
    for (int o = 1; o < SB; o <<= 1) {
        int x = (t >= o) ? s[t - o] : 0;
        __syncthreads();
        s[t] += x;
        __syncthreads();
    }
    if (i < NN) d_off[i] = s[t] - v;           // exclusive
    if (t == SB - 1) d_part[blockIdx.x] = s[t]; // block total
}

// scan stage 2: exclusive scan of the 98 partials (single block, 128 threads)
__global__ void k_scan2() {
    __shared__ int s[128];
    int t = threadIdx.x;
    int v = (t < NBLK) ? d_part[t] : 0;
    s[t] = v;
    __syncthreads();
    for (int o = 1; o < 128; o <<= 1) {
        int x = (t >= o) ? s[t - o] : 0;
        __syncthreads();
        s[t] += x;
        __syncthreads();
    }
    d_part[t] = s[t] - v;
}

// scan stage 3: add block offsets; init cursors; compute dis = rsqrt(deg)
__global__ void k_scan3() {
    int i = blockIdx.x * blockDim.x + threadIdx.x;
    if (i >= NN) return;
    int o = d_off[i] + d_part[i / SB];
    d_off[i] = o;
    d_cur[i] = o;
    d_dis[i] = rsqrtf((float)(d_cnt[i] + 1));   // +1 self loop
    if (i == 0) d_off[NN] = NE;
}

// fill CSR: srcs grouped by dst
__global__ void k_fill(const void* __restrict__ ei) {
    int e = blockIdx.x * blockDim.x + threadIdx.x;
    if (e >= NE) return;
    int s = eidx(ei, e);
    int d = eidx(ei, NE + e);
    int slot = atomicAdd(&d_cur[d], 1);
    d_srcs[slot] = s;
}

// per-graph node counts
__global__ void k_gcnt(const void* __restrict__ batch) {
    int i = blockIdx.x * blockDim.x + threadIdx.x;
    if (i >= NN) return;
    atomicAdd(&d_gcnt[eidx(batch, i)], 1);
}

// ---------------------------------------------------------------------------
// GEMM: hp = dis[:,None] * (A @ W).  64x128 tile / block, 256 thr, 8x4 / thr.
// Static smem: A tile 64x128 (32KB) + W chunk 32x128 (16KB) = 48KB.
__global__ void k_gemm(const float* __restrict__ A, const float* __restrict__ W,
                       float* __restrict__ hp, int n) {
    __shared__ float sA[64 * C];
    __shared__ float sW[32 * C];
    int tid = threadIdx.x;
    int row0 = blockIdx.x * 64;

    // stage A tile: 2048 float4, 8 per thread
    float4* sA4 = (float4*)sA;
    #pragma unroll
    for (int i = 0; i < 8; i++) {
        int idx = tid + i * 256;
        int r = idx >> 5, c4 = idx & 31;
        int gr = row0 + r;
        float4 v = make_float4(0.f, 0.f, 0.f, 0.f);
        if (gr < n) v = ((const float4*)(A + (size_t)gr * C))[c4];
        sA4[idx] = v;
    }

    int tx = tid & 31;   // col group (4 cols)
    int ty = tid >> 5;   // row group (8 rows)

    float acc[8][4];
    #pragma unroll
    for (int i = 0; i < 8; i++)
        #pragma unroll
        for (int j = 0; j < 4; j++) acc[i][j] = 0.0f;

    const float4* sWv = (const float4*)sW;
    for (int kc = 0; kc < 4; kc++) {
        __syncthreads();   // covers A staging (kc==0) and sW reuse (kc>0)
        // stage W rows [kc*32, kc*32+32): 1024 float4, 4 per thread
        const float4* Wg = (const float4*)(W + kc * 32 * C);
        #pragma unroll
        for (int i = 0; i < 4; i++) ((float4*)sW)[tid + i * 256] = Wg[tid + i * 256];
        __syncthreads();

        #pragma unroll
        for (int kk = 0; kk < 32; kk += 4) {
            float4 w0 = sWv[(kk + 0) * 32 + tx];
            float4 w1 = sWv[(kk + 1) * 32 + tx];
            float4 w2 = sWv[(kk + 2) * 32 + tx];
            float4 w3 = sWv[(kk + 3) * 32 + tx];
            #pragma unroll
            for (int i = 0; i < 8; i++) {
                float4 a = *(const float4*)(sA + (ty * 8 + i) * C + kc * 32 + kk);
                acc[i][0] += a.x * w0.x + a.y * w1.x + a.z * w2.x + a.w * w3.x;
                acc[i][1] += a.x * w0.y + a.y * w1.y + a.z * w2.y + a.w * w3.y;
                acc[i][2] += a.x * w0.z + a.y * w1.z + a.z * w2.z + a.w * w3.z;
                acc[i][3] += a.x * w0.w + a.y * w1.w + a.z * w2.w + a.w * w3.w;
            }
        }
    }

    #pragma unroll
    for (int i = 0; i < 8; i++) {
        int r = row0 + ty * 8 + i;
        if (r < n) {
            float ds = d_dis[r];
            float4 o = make_float4(acc[i][0] * ds, acc[i][1] * ds,
                                   acc[i][2] * ds, acc[i][3] * ds);
            *(float4*)(hp + (size_t)r * C + tx * 4) = o;
        }
    }
}

// ---------------------------------------------------------------------------
// Aggregate (gather, no atomics): one warp per dst node.
// h[v] = relu( dis[v] * (hp[v] + sum_{e in(v)} hp[src_e]) + b )
__global__ void k_agg(const float* __restrict__ hp, const float* __restrict__ b,
                      float* __restrict__ h) {
    int v = (blockIdx.x * blockDim.x + threadIdx.x) >> 5;
    if (v >= NN) return;
    int lane = threadIdx.x & 31;

    float4 acc = *(const float4*)(hp + (size_t)v * C + lane * 4);  // self loop
    int e = d_off[v], end = d_off[v + 1];

    for (; e + 3 < end; e += 4) {
        int s0 = d_srcs[e], s1 = d_srcs[e + 1], s2 = d_srcs[e + 2], s3 = d_srcs[e + 3];
        float4 m0 = *(const float4*)(hp + (size_t)s0 * C + lane * 4);
        float4 m1 = *(const float4*)(hp + (size_t)s1 * C + lane * 4);
        float4 m2 = *(const float4*)(hp + (size_t)s2 * C + lane * 4);
        float4 m3 = *(const float4*)(hp + (size_t)s3 * C + lane * 4);
        acc.x += m0.x + m1.x + m2.x + m3.x;
        acc.y += m0.y + m1.y + m2.y + m3.y;
        acc.z += m0.z + m1.z + m2.z + m3.z;
        acc.w += m0.w + m1.w + m2.w + m3.w;
    }
    for (; e < end; e++) {
        int s = d_srcs[e];
        float4 m = *(const float4*)(hp + (size_t)s * C + lane * 4);
        acc.x += m.x; acc.y += m.y; acc.z += m.z; acc.w += m.w;
    }

    float ds = d_dis[v];
    float4 bb = ((const float4*)b)[lane];
    float4 o;
    o.x = fmaxf(fmaf(ds, acc.x, bb.x), 0.0f);
    o.y = fmaxf(fmaf(ds, acc.y, bb.y), 0.0f);
    o.z = fmaxf(fmaf(ds, acc.z, bb.z), 0.0f);
    o.w = fmaxf(fmaf(ds, acc.w, bb.w), 0.0f);
    *(float4*)(h + (size_t)v * C + lane * 4) = o;
}

// ---------------------------------------------------------------------------
// pool sums per graph (scalar float atomics -> RED.E.ADD.F32)
__global__ void k_pool(const void* __restrict__ batch, const float* __restrict__ h) {
    int idx = blockIdx.x * blockDim.x + threadIdx.x;   // NN*32
    if (idx >= NN * 32) return;
    int v = idx >> 5, c4 = idx & 31;
    int g = eidx(batch, v);
    float4 val = *(const float4*)(h + (size_t)v * C + c4 * 4);
    float* p = d_pool + g * C + c4 * 4;
    atomicAdd(p + 0, val.x);
    atomicAdd(p + 1, val.y);
    atomicAdd(p + 2, val.z);
    atomicAdd(p + 3, val.w);
}

// head: pooled = sum/cnt; logits = pooled @ Wfc + bfc; log_softmax
__global__ void k_head(const float* __restrict__ Wfc, const float* __restrict__ bfc,
                       float* __restrict__ out) {
    int g = blockIdx.x;
    int t = threadIdx.x;   // 128
    __shared__ float sp[C];
    __shared__ float sl[OUTC];
    __shared__ float s_m, s_lse;
    float cnt = fmaxf((float)d_gcnt[g], 1.0f);
    sp[t] = d_pool[g * C + t] / cnt;
    __syncthreads();
    if (t < OUTC) {
        float a = bfc[t];
        #pragma unroll 8
        for (int k = 0; k < C; k++) a += sp[k] * Wfc[k * OUTC + t];
        sl[t] = a;
    }
    __syncthreads();
    if (t == 0) {
        float mx = sl[0];
        #pragma unroll
        for (int j = 1; j < OUTC; j++) mx = fmaxf(mx, sl[j]);
        float s = 0.0f;
        #pragma unroll
        for (int j = 0; j < OUTC; j++) s += expf(sl[j] - mx);
        s_m = mx;
        s_lse = logf(s);
    }
    __syncthreads();
    if (t < OUTC) out[g * OUTC + t] = sl[t] - s_m - s_lse;
}

// ---------------------------------------------------------------------------
extern "C" void kernel_launch(void* const* d_in, const int* in_sizes, int n_in,
                              void* d_out, int out_size) {
    const float* x     = (const float*)d_in[0];
    const void*  ei    = d_in[1];
    const void*  batch = d_in[2];
    const float* W1    = (const float*)d_in[3];
    const float* b1    = (const float*)d_in[4];
    const float* W2    = (const float*)d_in[5];
    const float* b2    = (const float*)d_in[6];
    const float* Wfc   = (const float*)d_in[7];
    const float* bfc   = (const float*)d_in[8];
    float* out = (float*)d_out;

    float *hp, *h;
    cudaGetSymbolAddress((void**)&hp, d_hp);
    cudaGetSymbolAddress((void**)&h, d_h);

    k_sniff<<<1, 1>>>((const unsigned int*)ei);
    k_setup<<<(NN + 255) / 256, 256>>>();
    k_count<<<(NE + 255) / 256, 256>>>(ei);
    k_scan1<<<NBLK, SB>>>();
    k_scan2<<<1, 128>>>();
    k_scan3<<<(NN + 255) / 256, 256>>>();
    k_fill<<<(NE + 255) / 256, 256>>>(ei);
    k_gcnt<<<(NN + 255) / 256, 256>>>(batch);

    // layer 1
    k_gemm<<<(NN + 63) / 64, 256>>>(x, W1, hp, NN);
    k_agg<<<(NN * 32 + 255) / 256, 256>>>(hp, b1, h);

    // layer 2
    k_gemm<<<(NN + 63) / 64, 256>>>(h, W2, hp, NN);
    k_agg<<<(NN * 32 + 255) / 256, 256>>>(hp, b2, h);

    // pool + head
    k_pool<<<(NN * 32 + 255) / 256, 256>>>(batch, h);
    k_head<<<NG, C>>>(Wfc, bfc, out);
}

// round 4
// speedup vs baseline: 1.1932x; 1.1932x over previous
#include <cuda_runtime.h>
#include <cuda_bf16.h>
#include <math.h>

#define NN 50000
#define NE 800000
#define C 128
#define OUTC 16
#define NG 128
#define SB 512
#define NBLK ((NN + SB - 1) / SB)   // 98

// GEMM tiling
#define BM 128
#define BK 32
#define SAPAD 40                    // padded row stride for sA

// -------- device scratch (no allocations allowed) --------
__device__ int   d_is64;
__device__ int   d_cnt[NN];          // incoming-edge counts
__device__ int   d_off[NN + 1];      // CSR offsets
__device__ int   d_cur[NN];          // fill cursors
__device__ int   d_srcs[NE];         // src ids grouped by dst
__device__ int   d_part[256];        // scan partials
__device__ int   d_gcnt[NG];         // nodes per graph
__device__ int   d_gstart[NG + 1];   // graph start offsets (batch is sorted)
__device__ float d_dis[NN];
__device__ __align__(16) float d_hp[(size_t)NN * C];
__device__ __align__(16) float d_h [(size_t)NN * C];

// index accessor: int64 vs int32 edge/batch arrays
__device__ __forceinline__ int eidx(const void* p, int pos) {
    return d_is64 ? (int)((const long long*)p)[pos] : ((const int*)p)[pos];
}

// ---------------------------------------------------------------------------
// dtype sniff: as int64, the odd 32-bit words (high halves) are all zero.
__global__ void k_sniff(const unsigned int* __restrict__ w) {
    int allz = 1;
    #pragma unroll
    for (int i = 0; i < 32; i++)
        if (w[2 * i + 1] != 0u) allz = 0;
    d_is64 = allz;
}

// zero per-call counters
__global__ void k_setup() {
    int i = blockIdx.x * blockDim.x + threadIdx.x;
    if (i < NN) d_cnt[i] = 0;
    if (i < NG) d_gcnt[i] = 0;
}

// fused: count incoming edges per dst + per-graph node counts
__global__ void k_count_gcnt(const void* __restrict__ ei, const void* __restrict__ batch) {
    int i = blockIdx.x * blockDim.x + threadIdx.x;
    if (i < NE) atomicAdd(&d_cnt[eidx(ei, NE + i)], 1);
    if (i < NN) atomicAdd(&d_gcnt[eidx(batch, i)], 1);
}

// scan stage 1: per-block exclusive scan of d_cnt -> d_off, totals -> d_part
__global__ void k_scan1() {
    __shared__ int s[SB];
    int t = threadIdx.x;
    int i = blockIdx.x * SB + t;
    int v = (i < NN) ? d_cnt[i] : 0;
    s[t] = v;
    __syncthreads();
    for (int o = 1; o < SB; o <<= 1) {
        int x = (t >= o) ? s[t - o] : 0;
        __syncthreads();
        s[t] += x;
        __syncthreads();
    }
    if (i < NN) d_off[i] = s[t] - v;            // exclusive
    if (t == SB - 1) d_part[blockIdx.x] = s[t]; // block total
}

// scan stage 2: exclusive scan of partials AND of per-graph counts -> gstart
__global__ void k_scan2() {
    __shared__ int s[128];
    __shared__ int q[128];
    int t = threadIdx.x;
    int v = (t < NBLK) ? d_part[t] : 0;
    int g = d_gcnt[t];                 // NG == 128
    s[t] = v;
    q[t] = g;
    __syncthreads();
    for (int o = 1; o < 128; o <<= 1) {
        int xs = (t >= o) ? s[t - o] : 0;
        int xq = (t >= o) ? q[t - o] : 0;
        __syncthreads();
        s[t] += xs;
        q[t] += xq;
        __syncthreads();
    }
    d_part[t] = s[t] - v;
    d_gstart[t] = q[t] - g;            // exclusive: start of graph t
    if (t == 127) d_gstart[NG] = NN;
}

// scan stage 3: add block offsets; init cursors; compute dis = rsqrt(deg)
__global__ void k_scan3() {
    int i = blockIdx.x * blockDim.x + threadIdx.x;
    if (i >= NN) return;
    int o = d_off[i] + d_part[i / SB];
    d_off[i] = o;
    d_cur[i] = o;
    d_dis[i] = rsqrtf((float)(d_cnt[i] + 1));   // +1 self loop
    if (i == 0) d_off[NN] = NE;
}

// fill CSR: srcs grouped by dst
__global__ void k_fill(const void* __restrict__ ei) {
    int e = blockIdx.x * blockDim.x + threadIdx.x;
    if (e >= NE) return;
    int s = eidx(ei, e);
    int d = eidx(ei, NE + e);
    int slot = atomicAdd(&d_cur[d], 1);
    d_srcs[slot] = s;
}

// ---------------------------------------------------------------------------
// GEMM: hp = dis[:,None] * (A @ W).
// 128x128 tile / block, 256 threads, 8x8 outputs per thread, BK=32 chunks.
// smem: sA 128x(32 pad 40) = 20KB, sW 32x128 = 16KB.
__global__ void __launch_bounds__(256)
k_gemm(const float* __restrict__ A, const float* __restrict__ W,
       float* __restrict__ hp, int n) {
    __shared__ float sA[BM * SAPAD];
    __shared__ float sW[BK * C];
    int tid = threadIdx.x;
    int row0 = blockIdx.x * BM;
    int tx = tid & 15;    // col group: cols tx*8 .. tx*8+8
    int ty = tid >> 4;    // row group: rows ty*8 .. ty*8+8

    float acc[8][8];
    #pragma unroll
    for (int i = 0; i < 8; i++)
        #pragma unroll
        for (int j = 0; j < 8; j++) acc[i][j] = 0.0f;

    for (int kc = 0; kc < C / BK; kc++) {
        __syncthreads();
        // stage A chunk: 128 rows x 32 cols; 1024 float4, 4 per thread
        #pragma unroll
        for (int p = 0; p < 4; p++) {
            int idx = tid + p * 256;         // 0..1023
            int r = idx >> 3;                // 0..127
            int c4 = idx & 7;                // 0..7
            int gr = row0 + r;
            float4 v = make_float4(0.f, 0.f, 0.f, 0.f);
            if (gr < n) v = *(const float4*)(A + (size_t)gr * C + kc * BK + c4 * 4);
            *(float4*)(sA + r * SAPAD + c4 * 4) = v;
        }
        // stage W chunk: rows [kc*32, kc*32+32), all 128 cols; 1024 float4
        const float4* Wg = (const float4*)(W + (size_t)kc * BK * C);
        #pragma unroll
        for (int p = 0; p < 4; p++)
            ((float4*)sW)[tid + p * 256] = Wg[tid + p * 256];
        __syncthreads();

        #pragma unroll
        for (int kk = 0; kk < BK; kk++) {
            float4 b0 = *(const float4*)(sW + kk * C + tx * 8);
            float4 b1 = *(const float4*)(sW + kk * C + tx * 8 + 4);
            float b[8] = {b0.x, b0.y, b0.z, b0.w, b1.x, b1.y, b1.z, b1.w};
            float a[8];
            #pragma unroll
            for (int i = 0; i < 8; i++) a[i] = sA[(ty * 8 + i) * SAPAD + kk];
            #pragma unroll
            for (int i = 0; i < 8; i++)
                #pragma unroll
                for (int j = 0; j < 8; j++)
                    acc[i][j] = fmaf(a[i], b[j], acc[i][j]);
        }
    }

    #pragma unroll
    for (int i = 0; i < 8; i++) {
        int r = row0 + ty * 8 + i;
        if (r < n) {
            float ds = d_dis[r];
            float4 o0 = make_float4(acc[i][0] * ds, acc[i][1] * ds,
                                    acc[i][2] * ds, acc[i][3] * ds);
            float4 o1 = make_float4(acc[i][4] * ds, acc[i][5] * ds,
                                    acc[i][6] * ds, acc[i][7] * ds);
            size_t off = (size_t)r * C + tx * 8;
            *(float4*)(hp + off) = o0;
            *(float4*)(hp + off + 4) = o1;
        }
    }
}

// ---------------------------------------------------------------------------
// Aggregate (gather, no atomics): one warp per dst node.
// h[v] = relu( dis[v] * (hp[v] + sum_{e in(v)} hp[src_e]) + b )
__global__ void k_agg(const float* __restrict__ hp, const float* __restrict__ b,
                      float* __restrict__ h) {
    int v = (blockIdx.x * blockDim.x + threadIdx.x) >> 5;
    if (v >= NN) return;
    int lane = threadIdx.x & 31;

    float4 acc = *(const float4*)(hp + (size_t)v * C + lane * 4);  // self loop
    int e = d_off[v], end = d_off[v + 1];

    for (; e + 3 < end; e += 4) {
        int s0 = d_srcs[e], s1 = d_srcs[e + 1], s2 = d_srcs[e + 2], s3 = d_srcs[e + 3];
        float4 m0 = *(const float4*)(hp + (size_t)s0 * C + lane * 4);
        float4 m1 = *(const float4*)(hp + (size_t)s1 * C + lane * 4);
        float4 m2 = *(const float4*)(hp + (size_t)s2 * C + lane * 4);
        float4 m3 = *(const float4*)(hp + (size_t)s3 * C + lane * 4);
        acc.x += m0.x + m1.x + m2.x + m3.x;
        acc.y += m0.y + m1.y + m2.y + m3.y;
        acc.z += m0.z + m1.z + m2.z + m3.z;
        acc.w += m0.w + m1.w + m2.w + m3.w;
    }
    for (; e < end; e++) {
        int s = d_srcs[e];
        float4 m = *(const float4*)(hp + (size_t)s * C + lane * 4);
        acc.x += m.x; acc.y += m.y; acc.z += m.z; acc.w += m.w;
    }

    float ds = d_dis[v];
    float4 bb = ((const float4*)b)[lane];
    float4 o;
    o.x = fmaxf(fmaf(ds, acc.x, bb.x), 0.0f);
    o.y = fmaxf(fmaf(ds, acc.y, bb.y), 0.0f);
    o.z = fmaxf(fmaf(ds, acc.z, bb.z), 0.0f);
    o.w = fmaxf(fmaf(ds, acc.w, bb.w), 0.0f);
    *(float4*)(h + (size_t)v * C + lane * 4) = o;
}

// ---------------------------------------------------------------------------
// Fused pool + FC head + log_softmax. batch is sorted, so graph g owns the
// contiguous node range [gstart[g], gstart[g+1]). No atomics.
__global__ void k_poolhead(const float* __restrict__ h, const float* __restrict__ Wfc,
                           const float* __restrict__ bfc, float* __restrict__ out) {
    int g = blockIdx.x;
    int t = threadIdx.x;   // 128
    __shared__ float sp[C];
    __shared__ float sl[OUTC];
    __shared__ float s_m, s_lse;

    int r0 = d_gstart[g], r1 = d_gstart[g + 1];
    float a0 = 0.0f, a1 = 0.0f;
    int r = r0;
    for (; r + 1 < r1; r += 2) {
        a0 += h[(size_t)r * C + t];
        a1 += h[(size_t)(r + 1) * C + t];
    }
    if (r < r1) a0 += h[(size_t)r * C + t];
    float cnt = fmaxf((float)(r1 - r0), 1.0f);
    sp[t] = (a0 + a1) / cnt;
    __syncthreads();

    if (t < OUTC) {
        float a = bfc[t];
        #pragma unroll 8
        for (int k = 0; k < C; k++) a += sp[k] * Wfc[k * OUTC + t];
        sl[t] = a;
    }
    __syncthreads();
    if (t == 0) {
        float mx = sl[0];
        #pragma unroll
        for (int j = 1; j < OUTC; j++) mx = fmaxf(mx, sl[j]);
        float s = 0.0f;
        #pragma unroll
        for (int j = 0; j < OUTC; j++) s += expf(sl[j] - mx);
        s_m = mx;
        s_lse = logf(s);
    }
    __syncthreads();
    if (t < OUTC) out[g * OUTC + t] = sl[t] - s_m - s_lse;
}

// ---------------------------------------------------------------------------
extern "C" void kernel_launch(void* const* d_in, const int* in_sizes, int n_in,
                              void* d_out, int out_size) {
    const float* x     = (const float*)d_in[0];
    const void*  ei    = d_in[1];
    const void*  batch = d_in[2];
    const float* W1    = (const float*)d_in[3];
    const float* b1    = (const float*)d_in[4];
    const float* W2    = (const float*)d_in[5];
    const float* b2    = (const float*)d_in[6];
    const float* Wfc   = (const float*)d_in[7];
    const float* bfc   = (const float*)d_in[8];
    float* out = (float*)d_out;

    float *hp, *h;
    cudaGetSymbolAddress((void**)&hp, d_hp);
    cudaGetSymbolAddress((void**)&h, d_h);

    k_sniff<<<1, 1>>>((const unsigned int*)ei);
    k_setup<<<(NN + 255) / 256, 256>>>();
    k_count_gcnt<<<(NE + 255) / 256, 256>>>(ei, batch);
    k_scan1<<<NBLK, SB>>>();
    k_scan2<<<1, 128>>>();
    k_scan3<<<(NN + 255) / 256, 256>>>();
    k_fill<<<(NE + 255) / 256, 256>>>(ei);

    // layer 1
    k_gemm<<<(NN + BM - 1) / BM, 256>>>(x, W1, hp, NN);
    k_agg<<<(NN * 32 + 255) / 256, 256>>>(hp, b1, h);

    // layer 2
    k_gemm<<<(NN + BM - 1) / BM, 256>>>(h, W2, hp, NN);
    k_agg<<<(NN * 32 + 255) / 256, 256>>>(hp, b2, h);

    // fused pool + head
    k_poolhead<<<NG, C>>>(h, Wfc, bfc, out);
}

// round 6
// speedup vs baseline: 1.6475x; 1.3807x over previous
#include <cuda_runtime.h>
#include <cuda_bf16.h>
#include <math.h>
#include <stdint.h>

#define NN 50000
#define NE 800000
#define C 128
#define OUTC 16
#define NG 128
#define SB 512
#define NBLK ((NN + SB - 1) / SB)   // 98

// GEMM tiling (tf32 tensor-core)
#define BM 128
#define BK 32
#define SA_STRIDE 36    // floats; bank = (4*row + col) % 32 -> conflict-free frags
#define SW_STRIDE 136   // floats; bank = (8*k + n) % 32   -> conflict-free frags

// -------- device scratch (no allocations allowed) --------
__device__ int   d_is64;
__device__ int   d_cnt[NN];          // incoming-edge counts
__device__ int   d_off[NN + 1];      // CSR offsets
__device__ int   d_cur[NN];          // fill cursors
__device__ int   d_srcs[NE];         // src ids grouped by dst
__device__ int   d_part[256];        // scan partials
__device__ int   d_gcnt[NG];         // nodes per graph
__device__ int   d_gstart[NG + 1];   // graph start offsets (batch is sorted)
__device__ float d_dis[NN];
__device__ __align__(16) float d_hp[(size_t)NN * C];
__device__ __align__(16) float d_h [(size_t)NN * C];

// index accessor: int64 vs int32 edge/batch arrays
__device__ __forceinline__ int eidx(const void* p, int pos) {
    return d_is64 ? (int)((const long long*)p)[pos] : ((const int*)p)[pos];
}

__device__ __forceinline__ uint32_t f2tf32(float x) {
    uint32_t r;
    asm("cvt.rna.tf32.f32 %0, %1;" : "=r"(r) : "f"(x));
    return r;
}

// ---------------------------------------------------------------------------
// dtype sniff: as int64, the odd 32-bit words (high halves) are all zero.
__global__ void k_sniff(const unsigned int* __restrict__ w) {
    int allz = 1;
    #pragma unroll
    for (int i = 0; i < 32; i++)
        if (w[2 * i + 1] != 0u) allz = 0;
    d_is64 = allz;
}

// zero per-call counters
__global__ void k_setup() {
    int i = blockIdx.x * blockDim.x + threadIdx.x;
    if (i < NN) d_cnt[i] = 0;
    if (i < NG) d_gcnt[i] = 0;
}

// fused: count incoming edges per dst + per-graph node counts
__global__ void k_count_gcnt(const void* __restrict__ ei, const void* __restrict__ batch) {
    int i = blockIdx.x * blockDim.x + threadIdx.x;
    if (i < NE) atomicAdd(&d_cnt[eidx(ei, NE + i)], 1);
    if (i < NN) atomicAdd(&d_gcnt[eidx(batch, i)], 1);
}

// scan stage 1: per-block exclusive scan of d_cnt -> d_off, totals -> d_part
__global__ void k_scan1() {
    __shared__ int s[SB];
    int t = threadIdx.x;
    int i = blockIdx.x * SB + t;
    int v = (i < NN) ? d_cnt[i] : 0;
    s[t] = v;
    __syncthreads();
    for (int o = 1; o < SB; o <<= 1) {
        int x = (t >= o) ? s[t - o] : 0;
        __syncthreads();
        s[t] += x;
        __syncthreads();
    }
    if (i < NN) d_off[i] = s[t] - v;            // exclusive
    if (t == SB - 1) d_part[blockIdx.x] = s[t]; // block total
}

// scan stage 2: exclusive scan of partials AND of per-graph counts -> gstart
__global__ void k_scan2() {
    __shared__ int s[128];
    __shared__ int q[128];
    int t = threadIdx.x;
    int v = (t < NBLK) ? d_part[t] : 0;
    int g = d_gcnt[t];                 // NG == 128
    s[t] = v;
    q[t] = g;
    __syncthreads();
    for (int o = 1; o < 128; o <<= 1) {
        int xs = (t >= o) ? s[t - o] : 0;
        int xq = (t >= o) ? q[t - o] : 0;
        __syncthreads();
        s[t] += xs;
        q[t] += xq;
        __syncthreads();
    }
    d_part[t] = s[t] - v;
    d_gstart[t] = q[t] - g;            // exclusive: start of graph t
    if (t == 127) d_gstart[NG] = NN;
}

// scan stage 3: add block offsets; init cursors; compute dis = rsqrt(deg)
__global__ void k_scan3() {
    int i = blockIdx.x * blockDim.x + threadIdx.x;
    if (i >= NN) return;
    int o = d_off[i] + d_part[i / SB];
    d_off[i] = o;
    d_cur[i] = o;
    d_dis[i] = rsqrtf((float)(d_cnt[i] + 1));   // +1 self loop
    if (i == 0) d_off[NN] = NE;
}

// fill CSR: srcs grouped by dst
__global__ void k_fill(const void* __restrict__ ei) {
    int e = blockIdx.x * blockDim.x + threadIdx.x;
    if (e >= NE) return;
    int s = eidx(ei, e);
    int d = eidx(ei, NE + e);
    int slot = atomicAdd(&d_cur[d], 1);
    d_srcs[slot] = s;
}

// ---------------------------------------------------------------------------
// TF32 tensor-core GEMM: hp = dis[:,None] * (A @ W).
// 128x128 block tile, 256 threads = 8 warps (2x4), warp tile 64x32.
// mma.m16n8k8.tf32: per warp per k8-step: 4 m-frags x 4 n-frags = 16 MMAs.
__global__ void __launch_bounds__(256)
k_gemm(const float* __restrict__ A, const float* __restrict__ W,
       float* __restrict__ hp, int n) {
    __shared__ uint32_t sA[BM * SA_STRIDE];   // tf32 bits, row-major, stride 36
    __shared__ uint32_t sW[BK * SW_STRIDE];   // tf32 bits, k-major, stride 136

    int tid = threadIdx.x;
    int lane = tid & 31;
    int wid = tid >> 5;
    int wm = wid >> 2;          // 0..1 : rows [wm*64, wm*64+64)
    int wn = wid & 3;           // 0..3 : cols [wn*32, wn*32+32)
    int g  = lane >> 2;         // groupID 0..7
    int tg = lane & 3;          // threadID-in-group 0..3
    int row0 = blockIdx.x * BM;

    float acc[4][4][4];         // [m-frag][n-frag][reg]
    #pragma unroll
    for (int i = 0; i < 4; i++)
        #pragma unroll
        for (int j = 0; j < 4; j++)
            #pragma unroll
            for (int r = 0; r < 4; r++) acc[i][j][r] = 0.0f;

    for (int kc = 0; kc < C / BK; kc++) {
        __syncthreads();
        // stage A chunk: 128 rows x 32 k; 1024 float4 reads, cvt to tf32
        #pragma unroll
        for (int p = 0; p < 4; p++) {
            int idx = tid + p * 256;        // 0..1023
            int r = idx >> 3;               // 0..127
            int c4 = idx & 7;               // 0..7
            int gr = row0 + r;
            float4 v = make_float4(0.f, 0.f, 0.f, 0.f);
            if (gr < n) v = *(const float4*)(A + (size_t)gr * C + kc * BK + c4 * 4);
            uint32_t* dst = sA + r * SA_STRIDE + c4 * 4;
            dst[0] = f2tf32(v.x); dst[1] = f2tf32(v.y);
            dst[2] = f2tf32(v.z); dst[3] = f2tf32(v.w);
        }
        // stage W chunk: 32 k x 128 n
        #pragma unroll
        for (int p = 0; p < 4; p++) {
            int idx = tid + p * 256;
            int k = idx >> 5;               // 0..31
            int n4 = idx & 31;              // 0..31
            float4 v = *(const float4*)(W + (size_t)(kc * BK + k) * C + n4 * 4);
            uint32_t* dst = sW + k * SW_STRIDE + n4 * 4;
            dst[0] = f2tf32(v.x); dst[1] = f2tf32(v.y);
            dst[2] = f2tf32(v.z); dst[3] = f2tf32(v.w);
        }
        __syncthreads();

        #pragma unroll
        for (int ks = 0; ks < BK / 8; ks++) {
            int kb = ks * 8;
            // load B fragments: 4 n-frags x 2 regs
            uint32_t bf[4][2];
            #pragma unroll
            for (int nt = 0; nt < 4; nt++) {
                int nn = wn * 32 + nt * 8 + g;
                bf[nt][0] = sW[(kb + tg) * SW_STRIDE + nn];
                bf[nt][1] = sW[(kb + tg + 4) * SW_STRIDE + nn];
            }
            // load A fragments: 4 m-frags x 4 regs
            uint32_t af[4][4];
            #pragma unroll
            for (int mt = 0; mt < 4; mt++) {
                int rbase = wm * 64 + mt * 16;
                af[mt][0] = sA[(rbase + g)     * SA_STRIDE + kb + tg];
                af[mt][1] = sA[(rbase + g + 8) * SA_STRIDE + kb + tg];
                af[mt][2] = sA[(rbase + g)     * SA_STRIDE + kb + tg + 4];
                af[mt][3] = sA[(rbase + g + 8) * SA_STRIDE + kb + tg + 4];
            }
            #pragma unroll
            for (int mt = 0; mt < 4; mt++)
                #pragma unroll
                for (int nt = 0; nt < 4; nt++) {
                    asm volatile(
                        "mma.sync.aligned.m16n8k8.row.col.f32.tf32.tf32.f32 "
                        "{%0,%1,%2,%3}, {%4,%5,%6,%7}, {%8,%9}, {%0,%1,%2,%3};"
                        : "+f"(acc[mt][nt][0]), "+f"(acc[mt][nt][1]),
                          "+f"(acc[mt][nt][2]), "+f"(acc[mt][nt][3])
                        : "r"(af[mt][0]), "r"(af[mt][1]), "r"(af[mt][2]), "r"(af[mt][3]),
                          "r"(bf[nt][0]), "r"(bf[nt][1]));
                }
        }
    }

    // epilogue: scale by dis[row], store float2 pairs
    #pragma unroll
    for (int mt = 0; mt < 4; mt++) {
        int r0 = row0 + wm * 64 + mt * 16 + g;
        int r1 = r0 + 8;
        float ds0 = (r0 < n) ? d_dis[r0] : 0.0f;
        float ds1 = (r1 < n) ? d_dis[r1] : 0.0f;
        #pragma unroll
        for (int nt = 0; nt < 4; nt++) {
            int col = wn * 32 + nt * 8 + tg * 2;
            if (r0 < n) {
                float2 o = make_float2(acc[mt][nt][0] * ds0, acc[mt][nt][1] * ds0);
                *(float2*)(hp + (size_t)r0 * C + col) = o;
            }
            if (r1 < n) {
                float2 o = make_float2(acc[mt][nt][2] * ds1, acc[mt][nt][3] * ds1);
                *(float2*)(hp + (size_t)r1 * C + col) = o;
            }
        }
    }
}

// ---------------------------------------------------------------------------
// Aggregate (gather, no atomics): one warp per dst node.
// h[v] = relu( dis[v] * (hp[v] + sum_{e in(v)} hp[src_e]) + b )
__global__ void k_agg(const float* __restrict__ hp, const float* __restrict__ b,
                      float* __restrict__ h) {
    int v = (blockIdx.x * blockDim.x + threadIdx.x) >> 5;
    if (v >= NN) return;
    int lane = threadIdx.x & 31;

    float4 acc = *(const float4*)(hp + (size_t)v * C + lane * 4);  // self loop
    int e = d_off[v], end = d_off[v + 1];

    for (; e + 3 < end; e += 4) {
        int s0 = d_srcs[e], s1 = d_srcs[e + 1], s2 = d_srcs[e + 2], s3 = d_srcs[e + 3];
        float4 m0 = *(const float4*)(hp + (size_t)s0 * C + lane * 4);
        float4 m1 = *(const float4*)(hp + (size_t)s1 * C + lane * 4);
        float4 m2 = *(const float4*)(hp + (size_t)s2 * C + lane * 4);
        float4 m3 = *(const float4*)(hp + (size_t)s3 * C + lane * 4);
        acc.x += m0.x + m1.x + m2.x + m3.x;
        acc.y += m0.y + m1.y + m2.y + m3.y;
        acc.z += m0.z + m1.z + m2.z + m3.z;
        acc.w += m0.w + m1.w + m2.w + m3.w;
    }
    for (; e < end; e++) {
        int s = d_srcs[e];
        float4 m = *(const float4*)(hp + (size_t)s * C + lane * 4);
        acc.x += m.x; acc.y += m.y; acc.z += m.z; acc.w += m.w;
    }

    float ds = d_dis[v];
    float4 bb = ((const float4*)b)[lane];
    float4 o;
    o.x = fmaxf(fmaf(ds, acc.x, bb.x), 0.0f);
    o.y = fmaxf(fmaf(ds, acc.y, bb.y), 0.0f);
    o.z = fmaxf(fmaf(ds, acc.z, bb.z), 0.0f);
    o.w = fmaxf(fmaf(ds, acc.w, bb.w), 0.0f);
    *(float4*)(h + (size_t)v * C + lane * 4) = o;
}

// ---------------------------------------------------------------------------
// Fused pool + FC head + log_softmax. batch is sorted, so graph g owns the
// contiguous node range [gstart[g], gstart[g+1]). No atomics.
__global__ void k_poolhead(const float* __restrict__ h, const float* __restrict__ Wfc,
                           const float* __restrict__ bfc, float* __restrict__ out) {
    int g = blockIdx.x;
    int t = threadIdx.x;   // 128
    __shared__ float sp[C];
    __shared__ float sl[OUTC];
    __shared__ float s_m, s_lse;

    int r0 = d_gstart[g], r1 = d_gstart[g + 1];
    float a0 = 0.0f, a1 = 0.0f;
    int r = r0;
    for (; r + 1 < r1; r += 2) {
        a0 += h[(size_t)r * C + t];
        a1 += h[(size_t)(r + 1) * C + t];
    }
    if (r < r1) a0 += h[(size_t)r * C + t];
    float cnt = fmaxf((float)(r1 - r0), 1.0f);
    sp[t] = (a0 + a1) / cnt;
    __syncthreads();

    if (t < OUTC) {
        float a = bfc[t];
        #pragma unroll 8
        for (int k = 0; k < C; k++) a += sp[k] * Wfc[k * OUTC + t];
        sl[t] = a;
    }
    __syncthreads();
    if (t == 0) {
        float mx = sl[0];
        #pragma unroll
        for (int j = 1; j < OUTC; j++) mx = fmaxf(mx, sl[j]);
        float s = 0.0f;
        #pragma unroll
        for (int j = 0; j < OUTC; j++) s += expf(sl[j] - mx);
        s_m = mx;
        s_lse = logf(s);
    }
    __syncthreads();
    if (t < OUTC) out[g * OUTC + t] = sl[t] - s_m - s_lse;
}

// ---------------------------------------------------------------------------
extern "C" void kernel_launch(void* const* d_in, const int* in_sizes, int n_in,
                              void* d_out, int out_size) {
    const float* x     = (const float*)d_in[0];
    const void*  ei    = d_in[1];
    const void*  batch = d_in[2];
    const float* W1    = (const float*)d_in[3];
    const float* b1    = (const float*)d_in[4];
    const float* W2    = (const float*)d_in[5];
    const float* b2    = (const float*)d_in[6];
    const float* Wfc   = (const float*)d_in[7];
    const float* bfc   = (const float*)d_in[8];
    float* out = (float*)d_out;

    float *hp, *h;
    cudaGetSymbolAddress((void**)&hp, d_hp);
    cudaGetSymbolAddress((void**)&h, d_h);

    k_sniff<<<1, 1>>>((const unsigned int*)ei);
    k_setup<<<(NN + 255) / 256, 256>>>();
    k_count_gcnt<<<(NE + 255) / 256, 256>>>(ei, batch);
    k_scan1<<<NBLK, SB>>>();
    k_scan2<<<1, 128>>>();
    k_scan3<<<(NN + 255) / 256, 256>>>();
    k_fill<<<(NE + 255) / 256, 256>>>(ei);

    // layer 1
    k_gemm<<<(NN + BM - 1) / BM, 256>>>(x, W1, hp, NN);
    k_agg<<<(NN * 32 + 255) / 256, 256>>>(hp, b1, h);

    // layer 2
    k_gemm<<<(NN + BM - 1) / BM, 256>>>(h, W2, hp, NN);
    k_agg<<<(NN * 32 + 255) / 256, 256>>>(hp, b2, h);

    // fused pool + head
    k_poolhead<<<NG, C>>>(h, Wfc, bfc, out);
}

// round 7
// speedup vs baseline: 1.9452x; 1.1807x over previous
#include <cuda_runtime.h>
#include <cuda_bf16.h>
#include <cuda_fp16.h>
#include <math.h>
#include <stdint.h>

#define NN 50000
#define NE 800000
#define C 128
#define OUTC 16
#define NG 128
#define SB 512
#define NBLK ((NN + SB - 1) / SB)   // 98

// GEMM tiling (tf32 tensor-core)
#define BM 128
#define BK 32
#define SA_STRIDE 36    // floats; bank = (4*row + col) % 32 -> conflict-free frags
#define SW_STRIDE 136   // floats; bank = (8*k + n) % 32   -> conflict-free frags

// -------- device scratch (no allocations allowed) --------
__device__ int   d_is64;
__device__ int   d_cnt[NN];          // incoming-edge counts
__device__ int   d_off[NN + 1];      // CSR offsets
__device__ int   d_cur[NN];          // fill cursors
__device__ int   d_srcs[NE];         // src ids grouped by dst
__device__ int   d_part[256];        // scan partials
__device__ int   d_gcnt[NG];         // nodes per graph
__device__ int   d_gstart[NG + 1];   // graph start offsets (batch is sorted)
__device__ float d_dis[NN];
__device__ __align__(16) __half d_hp[(size_t)NN * C];
__device__ __align__(16) __half d_h [(size_t)NN * C];

// index accessor: int64 vs int32 edge/batch arrays
__device__ __forceinline__ int eidx(const void* p, int pos) {
    return d_is64 ? (int)((const long long*)p)[pos] : ((const int*)p)[pos];
}

__device__ __forceinline__ uint32_t f2tf32(float x) {
    uint32_t r;
    asm("cvt.rna.tf32.f32 %0, %1;" : "=r"(r) : "f"(x));
    return r;
}

__device__ __forceinline__ float4 h4tof4(uint2 u) {
    __half2 a = *reinterpret_cast<__half2*>(&u.x);
    __half2 b = *reinterpret_cast<__half2*>(&u.y);
    float2 fa = __half22float2(a), fb = __half22float2(b);
    return make_float4(fa.x, fa.y, fb.x, fb.y);
}

__device__ __forceinline__ uint2 f4toh4(float4 f) {
    __half2 a = __floats2half2_rn(f.x, f.y);
    __half2 b = __floats2half2_rn(f.z, f.w);
    uint2 u;
    u.x = *reinterpret_cast<uint32_t*>(&a);
    u.y = *reinterpret_cast<uint32_t*>(&b);
    return u;
}

// ---------------------------------------------------------------------------
// setup: zero counters; thread 0 sniffs index dtype (int64 high words == 0)
__global__ void k_setup(const unsigned int* __restrict__ w) {
    int i = blockIdx.x * blockDim.x + threadIdx.x;
    if (i == 0) {
        int allz = 1;
        #pragma unroll
        for (int j = 0; j < 32; j++)
            if (w[2 * j + 1] != 0u) allz = 0;
        d_is64 = allz;
    }
    if (i < NN) d_cnt[i] = 0;
    if (i < NG) d_gcnt[i] = 0;
}

// fused: count incoming edges per dst + per-graph node counts
__global__ void k_count_gcnt(const void* __restrict__ ei, const void* __restrict__ batch) {
    int i = blockIdx.x * blockDim.x + threadIdx.x;
    if (i < NE) atomicAdd(&d_cnt[eidx(ei, NE + i)], 1);
    if (i < NN) atomicAdd(&d_gcnt[eidx(batch, i)], 1);
}

// scan stage 1 (shfl-based): per-block exclusive scan of d_cnt -> d_off
__global__ void k_scan1() {
    __shared__ int wsum[16];
    int t = threadIdx.x;
    int i = blockIdx.x * SB + t;
    int v = (i < NN) ? d_cnt[i] : 0;
    int x = v;
    #pragma unroll
    for (int o = 1; o < 32; o <<= 1) {
        int y = __shfl_up_sync(0xffffffffu, x, o);
        if ((t & 31) >= o) x += y;
    }
    if ((t & 31) == 31) wsum[t >> 5] = x;
    __syncthreads();
    if (t < 16) {
        int y = wsum[t];
        #pragma unroll
        for (int o = 1; o < 16; o <<= 1) {
            int z = __shfl_up_sync(0xffffu, y, o);
            if (t >= o) y += z;
        }
        wsum[t] = y;
    }
    __syncthreads();
    int base = (t >= 32) ? wsum[(t >> 5) - 1] : 0;
    int incl = x + base;
    if (i < NN) d_off[i] = incl - v;            // exclusive
    if (t == SB - 1) d_part[blockIdx.x] = incl; // block total
}

// scan stage 2: exclusive scan of partials AND of per-graph counts -> gstart
__global__ void k_scan2() {
    __shared__ int s[128];
    __shared__ int q[128];
    int t = threadIdx.x;
    int v = (t < NBLK) ? d_part[t] : 0;
    int g = d_gcnt[t];                 // NG == 128
    s[t] = v;
    q[t] = g;
    __syncthreads();
    for (int o = 1; o < 128; o <<= 1) {
        int xs = (t >= o) ? s[t - o] : 0;
        int xq = (t >= o) ? q[t - o] : 0;
        __syncthreads();
        s[t] += xs;
        q[t] += xq;
        __syncthreads();
    }
    d_part[t] = s[t] - v;
    d_gstart[t] = q[t] - g;            // exclusive: start of graph t
    if (t == 127) d_gstart[NG] = NN;
}

// scan stage 3: add block offsets; init cursors; compute dis = rsqrt(deg)
__global__ void k_scan3() {
    int i = blockIdx.x * blockDim.x + threadIdx.x;
    if (i >= NN) return;
    int o = d_off[i] + d_part[i / SB];
    d_off[i] = o;
    d_cur[i] = o;
    d_dis[i] = rsqrtf((float)(d_cnt[i] + 1));   // +1 self loop
    if (i == 0) d_off[NN] = NE;
}

// fill CSR: srcs grouped by dst
__global__ void k_fill(const void* __restrict__ ei) {
    int e = blockIdx.x * blockDim.x + threadIdx.x;
    if (e >= NE) return;
    int s = eidx(ei, e);
    int d = eidx(ei, NE + e);
    int slot = atomicAdd(&d_cur[d], 1);
    d_srcs[slot] = s;
}

// ---------------------------------------------------------------------------
// TF32 tensor-core GEMM: hp(half) = dis[:,None] * (A @ W), A fp32 or fp16.
// 128x128 block tile, 256 threads = 8 warps (2x4), warp tile 64x32.
template <typename T>
__global__ void __launch_bounds__(256)
k_gemm(const T* __restrict__ A, const float* __restrict__ W,
       __half* __restrict__ hp, int n) {
    __shared__ uint32_t sA[BM * SA_STRIDE];   // tf32 bits, row-major, stride 36
    __shared__ uint32_t sW[BK * SW_STRIDE];   // tf32 bits, k-major, stride 136

    int tid = threadIdx.x;
    int lane = tid & 31;
    int wid = tid >> 5;
    int wm = wid >> 2;          // 0..1 : rows [wm*64, wm*64+64)
    int wn = wid & 3;           // 0..3 : cols [wn*32, wn*32+32)
    int g  = lane >> 2;         // groupID 0..7
    int tg = lane & 3;          // threadID-in-group 0..3
    int row0 = blockIdx.x * BM;

    float acc[4][4][4];         // [m-frag][n-frag][reg]
    #pragma unroll
    for (int i = 0; i < 4; i++)
        #pragma unroll
        for (int j = 0; j < 4; j++)
            #pragma unroll
            for (int r = 0; r < 4; r++) acc[i][j][r] = 0.0f;

    for (int kc = 0; kc < C / BK; kc++) {
        __syncthreads();
        // stage A chunk: 128 rows x 32 k; 4 elems per thread-step, cvt to tf32
        #pragma unroll
        for (int p = 0; p < 4; p++) {
            int idx = tid + p * 256;        // 0..1023
            int r = idx >> 3;               // 0..127
            int c4 = idx & 7;               // 0..7
            int gr = row0 + r;
            float4 v = make_float4(0.f, 0.f, 0.f, 0.f);
            if (gr < n) {
                if constexpr (sizeof(T) == 4) {
                    v = *(const float4*)((const float*)A + (size_t)gr * C + kc * BK + c4 * 4);
                } else {
                    uint2 u = *(const uint2*)((const __half*)A + (size_t)gr * C + kc * BK + c4 * 4);
                    v = h4tof4(u);
                }
            }
            uint32_t* dst = sA + r * SA_STRIDE + c4 * 4;
            dst[0] = f2tf32(v.x); dst[1] = f2tf32(v.y);
            dst[2] = f2tf32(v.z); dst[3] = f2tf32(v.w);
        }
        // stage W chunk: 32 k x 128 n
        #pragma unroll
        for (int p = 0; p < 4; p++) {
            int idx = tid + p * 256;
            int k = idx >> 5;               // 0..31
            int n4 = idx & 31;              // 0..31
            float4 v = *(const float4*)(W + (size_t)(kc * BK + k) * C + n4 * 4);
            uint32_t* dst = sW + k * SW_STRIDE + n4 * 4;
            dst[0] = f2tf32(v.x); dst[1] = f2tf32(v.y);
            dst[2] = f2tf32(v.z); dst[3] = f2tf32(v.w);
        }
        __syncthreads();

        #pragma unroll
        for (int ks = 0; ks < BK / 8; ks++) {
            int kb = ks * 8;
            uint32_t bf[4][2];
            #pragma unroll
            for (int nt = 0; nt < 4; nt++) {
                int nn = wn * 32 + nt * 8 + g;
                bf[nt][0] = sW[(kb + tg) * SW_STRIDE + nn];
                bf[nt][1] = sW[(kb + tg + 4) * SW_STRIDE + nn];
            }
            uint32_t af[4][4];
            #pragma unroll
            for (int mt = 0; mt < 4; mt++) {
                int rbase = wm * 64 + mt * 16;
                af[mt][0] = sA[(rbase + g)     * SA_STRIDE + kb + tg];
                af[mt][1] = sA[(rbase + g + 8) * SA_STRIDE + kb + tg];
                af[mt][2] = sA[(rbase + g)     * SA_STRIDE + kb + tg + 4];
                af[mt][3] = sA[(rbase + g + 8) * SA_STRIDE + kb + tg + 4];
            }
            #pragma unroll
            for (int mt = 0; mt < 4; mt++)
                #pragma unroll
                for (int nt = 0; nt < 4; nt++) {
                    asm volatile(
                        "mma.sync.aligned.m16n8k8.row.col.f32.tf32.tf32.f32 "
                        "{%0,%1,%2,%3}, {%4,%5,%6,%7}, {%8,%9}, {%0,%1,%2,%3};"
                        : "+f"(acc[mt][nt][0]), "+f"(acc[mt][nt][1]),
                          "+f"(acc[mt][nt][2]), "+f"(acc[mt][nt][3])
                        : "r"(af[mt][0]), "r"(af[mt][1]), "r"(af[mt][2]), "r"(af[mt][3]),
                          "r"(bf[nt][0]), "r"(bf[nt][1]));
                }
        }
    }

    // epilogue: scale by dis[row], store half2 pairs
    #pragma unroll
    for (int mt = 0; mt < 4; mt++) {
        int r0 = row0 + wm * 64 + mt * 16 + g;
        int r1 = r0 + 8;
        float ds0 = (r0 < n) ? d_dis[r0] : 0.0f;
        float ds1 = (r1 < n) ? d_dis[r1] : 0.0f;
        #pragma unroll
        for (int nt = 0; nt < 4; nt++) {
            int col = wn * 32 + nt * 8 + tg * 2;
            if (r0 < n) {
                __half2 o = __floats2half2_rn(acc[mt][nt][0] * ds0, acc[mt][nt][1] * ds0);
                *(__half2*)(hp + (size_t)r0 * C + col) = o;
            }
            if (r1 < n) {
                __half2 o = __floats2half2_rn(acc[mt][nt][2] * ds1, acc[mt][nt][3] * ds1);
                *(__half2*)(hp + (size_t)r1 * C + col) = o;
            }
        }
    }
}

// ---------------------------------------------------------------------------
// Aggregate (gather, no atomics): one warp per dst node, fp16 in/out, fp32 acc.
// h[v] = relu( dis[v] * (hp[v] + sum_{e in(v)} hp[src_e]) + b )
__global__ void k_agg(const __half* __restrict__ hp, const float* __restrict__ b,
                      __half* __restrict__ h) {
    int v = (blockIdx.x * blockDim.x + threadIdx.x) >> 5;
    if (v >= NN) return;
    int lane = threadIdx.x & 31;

    float4 acc = h4tof4(*(const uint2*)(hp + (size_t)v * C + lane * 4));  // self loop
    int e = d_off[v], end = d_off[v + 1];

    for (; e + 3 < end; e += 4) {
        int s0 = d_srcs[e], s1 = d_srcs[e + 1], s2 = d_srcs[e + 2], s3 = d_srcs[e + 3];
        float4 m0 = h4tof4(*(const uint2*)(hp + (size_t)s0 * C + lane * 4));
        float4 m1 = h4tof4(*(const uint2*)(hp + (size_t)s1 * C + lane * 4));
        float4 m2 = h4tof4(*(const uint2*)(hp + (size_t)s2 * C + lane * 4));
        float4 m3 = h4tof4(*(const uint2*)(hp + (size_t)s3 * C + lane * 4));
        acc.x += m0.x + m1.x + m2.x + m3.x;
        acc.y += m0.y + m1.y + m2.y + m3.y;
        acc.z += m0.z + m1.z + m2.z + m3.z;
        acc.w += m0.w + m1.w + m2.w + m3.w;
    }
    for (; e < end; e++) {
        int s = d_srcs[e];
        float4 m = h4tof4(*(const uint2*)(hp + (size_t)s * C + lane * 4));
        acc.x += m.x; acc.y += m.y; acc.z += m.z; acc.w += m.w;
    }

    float ds = d_dis[v];
    float4 bb = ((const float4*)b)[lane];
    float4 o;
    o.x = fmaxf(fmaf(ds, acc.x, bb.x), 0.0f);
    o.y = fmaxf(fmaf(ds, acc.y, bb.y), 0.0f);
    o.z = fmaxf(fmaf(ds, acc.z, bb.z), 0.0f);
    o.w = fmaxf(fmaf(ds, acc.w, bb.w), 0.0f);
    *(uint2*)(h + (size_t)v * C + lane * 4) = f4toh4(o);
}

// ---------------------------------------------------------------------------
// Fused pool + FC head + log_softmax. batch is sorted, so graph g owns the
// contiguous node range [gstart[g], gstart[g+1]). No atomics.
__global__ void k_poolhead(const __half* __restrict__ h, const float* __restrict__ Wfc,
                           const float* __restrict__ bfc, float* __restrict__ out) {
    int g = blockIdx.x;
    int t = threadIdx.x;   // 128
    __shared__ float sp[C];
    __shared__ float sl[OUTC];
    __shared__ float s_m, s_lse;

    int r0 = d_gstart[g], r1 = d_gstart[g + 1];
    float a0 = 0.0f, a1 = 0.0f;
    int r = r0;
    for (; r + 1 < r1; r += 2) {
        a0 += __half2float(h[(size_t)r * C + t]);
        a1 += __half2float(h[(size_t)(r + 1) * C + t]);
    }
    if (r < r1) a0 += __half2float(h[(size_t)r * C + t]);
    float cnt = fmaxf((float)(r1 - r0), 1.0f);
    sp[t] = (a0 + a1) / cnt;
    __syncthreads();

    if (t < OUTC) {
        float a = bfc[t];
        #pragma unroll 8
        for (int k = 0; k < C; k++) a += sp[k] * Wfc[k * OUTC + t];
        sl[t] = a;
    }
    __syncthreads();
    if (t == 0) {
        float mx = sl[0];
        #pragma unroll
        for (int j = 1; j < OUTC; j++) mx = fmaxf(mx, sl[j]);
        float s = 0.0f;
        #pragma unroll
        for (int j = 0; j < OUTC; j++) s += expf(sl[j] - mx);
        s_m = mx;
        s_lse = logf(s);
    }
    __syncthreads();
    if (t < OUTC) out[g * OUTC + t] = sl[t] - s_m - s_lse;
}

// ---------------------------------------------------------------------------
extern "C" void kernel_launch(void* const* d_in, const int* in_sizes, int n_in,
                              void* d_out, int out_size) {
    const float* x     = (const float*)d_in[0];
    const void*  ei    = d_in[1];
    const void*  batch = d_in[2];
    const float* W1    = (const float*)d_in[3];
    const float* b1    = (const float*)d_in[4];
    const float* W2    = (const float*)d_in[5];
    const float* b2    = (const float*)d_in[6];
    const float* Wfc   = (const float*)d_in[7];
    const float* bfc   = (const float*)d_in[8];
    float* out = (float*)d_out;

    __half *hp, *h;
    cudaGetSymbolAddress((void**)&hp, d_hp);
    cudaGetSymbolAddress((void**)&h, d_h);

    k_setup<<<(NN + 255) / 256, 256>>>((const unsigned int*)ei);
    k_count_gcnt<<<(NE + 255) / 256, 256>>>(ei, batch);
    k_scan1<<<NBLK, SB>>>();
    k_scan2<<<1, 128>>>();
    k_scan3<<<(NN + 255) / 256, 256>>>();
    k_fill<<<(NE + 255) / 256, 256>>>(ei);

    // layer 1
    k_gemm<float><<<(NN + BM - 1) / BM, 256>>>(x, W1, hp, NN);
    k_agg<<<(NN * 32 + 255) / 256, 256>>>(hp, b1, h);

    // layer 2
    k_gemm<__half><<<(NN + BM - 1) / BM, 256>>>(h, W2, hp, NN);
    k_agg<<<(NN * 32 + 255) / 256, 256>>>(hp, b2, h);

    // fused pool + head
    k_poolhead<<<NG, C>>>(h, Wfc, bfc, out);
}